// round 5
// baseline (speedup 1.0000x reference)
#include <cuda_runtime.h>
#include <math.h>

#define B_    64
#define T_    512
#define EMB_  256
#define HD_   256
#define G4_   1024
#define TAGS_ 11
#define NEGV  (-10000.0f)

// ---------------- scratch (static device globals; no allocs) ----------------
__device__ float g_Gx[(long)2 * T_ * B_ * G4_];                 // [dir][t][gate][unit][b]
__device__ __align__(16) float g_Hout[(long)2 * T_ * B_ * HD_]; // [dir][t][unit][b]
__device__ __align__(16) float2 g_hbuf2[2 * 2 * 8192];          // [dir][parity][k2=unitpair][b]
__device__ float g_feats[T_ * B_ * TAGS_];
#define LSTM_NB 128
__device__ unsigned g_flagsF[LSTM_NB];
__device__ unsigned g_flagsB[LSTM_NB];

// ---------------- packed f32x2 helpers ----------------
__device__ __forceinline__ void ffma2(unsigned long long& d,
                                      unsigned long long a,
                                      unsigned long long b) {
    asm("fma.rn.f32x2 %0, %1, %2, %0;" : "+l"(d) : "l"(a), "l"(b));
}
__device__ __forceinline__ float2 upk(unsigned long long v) {
    float2 f; asm("mov.b64 {%0, %1}, %2;" : "=f"(f.x), "=f"(f.y) : "l"(v)); return f;
}

// ---------------- release/acquire flag ops ----------------
__device__ __forceinline__ unsigned ld_acq(const unsigned* p) {
    unsigned v;
    asm volatile("ld.global.acquire.gpu.u32 %0, [%1];" : "=r"(v) : "l"(p));
    return v;
}
__device__ __forceinline__ void st_rel(unsigned* p, unsigned v) {
    asm volatile("st.global.release.gpu.u32 [%0], %1;" :: "l"(p), "r"(v) : "memory");
}

// =====================================================================
// K1: Gx = embed[sent] @ Wih.T + b, written as [dir][t][gate][unit][b].
// =====================================================================
__global__ void gx_kernel(const int* __restrict__ sent,
                          const float* __restrict__ embed,
                          const float* __restrict__ Wf, const float* __restrict__ bf,
                          const float* __restrict__ Wb, const float* __restrict__ bb)
{
    __shared__ __align__(16) float As[64 * 36];
    __shared__ __align__(16) float Bs[128 * 36];
    __shared__ int toks[64];

    const int t     = blockIdx.x;
    const int dir   = blockIdx.y >> 3;
    const int gcol0 = (blockIdx.y & 7) * 128;
    const float* __restrict__ W    = dir ? Wb : Wf;
    const float* __restrict__ bias = dir ? bb : bf;

    const int tid = threadIdx.x;
    if (tid < 64) toks[tid] = sent[tid * T_ + t];
    __syncthreads();

    const int rowg = tid & 7;
    const int colg = tid >> 3;

    unsigned long long acc[8][4];
#pragma unroll
    for (int i = 0; i < 8; i++)
#pragma unroll
        for (int j = 0; j < 4; j++) acc[i][j] = 0ull;

    for (int k0 = 0; k0 < EMB_; k0 += 32) {
#pragma unroll
        for (int i = 0; i < 2; i++) {
            int e = tid + i * 256, r = e >> 3, seg = e & 7;
            float4 va = *(const float4*)(embed + (long)toks[r] * EMB_ + k0 + seg * 4);
            *(float4*)&As[r * 36 + seg * 4] = va;
        }
#pragma unroll
        for (int i = 0; i < 4; i++) {
            int e = tid + i * 256, r = e >> 3, seg = e & 7;
            float4 vb = *(const float4*)(W + (long)(gcol0 + r) * EMB_ + k0 + seg * 4);
            *(float4*)&Bs[r * 36 + seg * 4] = vb;
        }
        __syncthreads();
#pragma unroll
        for (int k4 = 0; k4 < 8; k4++) {
            ulonglong2 bv[4];
#pragma unroll
            for (int j = 0; j < 4; j++)
                bv[j] = *(const ulonglong2*)&Bs[(colg * 4 + j) * 36 + k4 * 4];
#pragma unroll
            for (int i = 0; i < 8; i++) {
                ulonglong2 av = *(const ulonglong2*)&As[(rowg + 8 * i) * 36 + k4 * 4];
#pragma unroll
                for (int j = 0; j < 4; j++) {
                    ffma2(acc[i][j], av.x, bv[j].x);
                    ffma2(acc[i][j], av.y, bv[j].y);
                }
            }
        }
        __syncthreads();
    }

    const long tb = (long)dir * T_ + t;
#pragma unroll
    for (int j = 0; j < 4; j++) {
        int col = gcol0 + colg * 4 + j;
        float bsv = bias[col];
        long obase = ((tb * 4 + (col >> 8)) * 256 + (col & 255)) * 64;
#pragma unroll
        for (int i = 0; i < 8; i++) {
            float2 p = upk(acc[i][j]);
            g_Gx[obase + rowg + 8 * i] = p.x + p.y + bsv;
        }
    }
}

// =====================================================================
// K2: persistent BiLSTM, 128 CTAs x 256 threads, BOTH directions per CTA.
// CTA c owns fwd units {2c,2c+1} AND bwd units {2c,2c+1}.
// thread = (b = tid&63, gate = tid>>6). Phases F then B each step; each
// chain's barrier latency hides behind the other chain's compute.
// smem floats: W 4096 | hs 16384 | ex 512 | shp 128  = 84480 B
// =====================================================================
#define SMF_W   0
#define SMF_HS  4096
#define SMF_EX  (4096 + 16384)
#define SMF_SHP (SMF_EX + 512)
#define LSTM_SMEM ((SMF_SHP + 128) * 4)

__global__ void __launch_bounds__(256, 1)
lstm_kernel(const float* __restrict__ Whh_f, const float* __restrict__ Whh_b,
            const float* __restrict__ h0f, const float* __restrict__ c0f,
            const float* __restrict__ h0b, const float* __restrict__ c0b,
            const float* __restrict__ mask)
{
    extern __shared__ __align__(16) float sm[];
    float*  Wsh = sm + SMF_W;      // [row=dir*8+gate*2+u][k 0..255]
    float*  hs  = sm + SMF_HS;     // float2[k2][b] viewed as floats
    float*  ex  = sm + SMF_EX;     // [gate][u][b]
    float*  shp = sm + SMF_SHP;    // [u][b]

    const int c    = blockIdx.x;
    const int tid  = threadIdx.x;
    const int b    = tid & 63;
    const int gate = tid >> 6;
    const int u    = gate & 1;     // role for updater threads (tid<128)

    // weight preload: row = dir*8 + g*2 + uu  <-  Whh_dir[g*256 + 2c+uu][:]
#pragma unroll
    for (int i = 0; i < 4; i++) {
        int f   = tid + i * 256;       // float4 idx 0..1023
        int row = f >> 6;
        int k4  = f & 63;
        int d   = row >> 3;
        int g   = (row >> 1) & 3;
        int uu  = row & 1;
        const float* W = d ? Whh_b : Whh_f;
        float4 w = *(const float4*)(W + (long)(g * 256 + 2 * c + uu) * HD_ + k4 * 4);
        *(float4*)&Wsh[row * 256 + k4 * 4] = w;
    }

    float2* hbufF = g_hbuf2;            // [parity][8192]
    float2* hbufB = g_hbuf2 + 2 * 8192;

    __shared__ unsigned sbF, sbB;
    if (tid == 0) { sbF = ld_acq(&g_flagsF[c]); sbB = ld_acq(&g_flagsB[c]); }
    __syncthreads();
    const unsigned baseF = sbF, baseB = sbB;

    // state held by updater threads (tid<128): (b, u)
    float hF = 0.f, cF = 0.f, hB = 0.f, cB = 0.f;
    if (tid < 128) {
        hF = h0f[b * HD_ + 2 * c + u];  cF = c0f[b * HD_ + 2 * c + u];
        hB = h0b[b * HD_ + 2 * c + u];  cB = c0b[b * HD_ + 2 * c + u];
    }
    // initial publish to parity 0
    if (tid < 128) shp[u * 64 + b] = hF;
    __syncthreads();
    if (tid < 64) __stcg(&hbufF[c * 64 + tid], make_float2(shp[tid], shp[64 + tid]));
    __syncthreads();
    if (tid < 128) shp[u * 64 + b] = hB;
    __syncthreads();
    if (tid < 64) __stcg(&hbufB[c * 64 + tid], make_float2(shp[tid], shp[64 + tid]));
    __syncthreads();
    if (tid == 0) { st_rel(&g_flagsF[c], baseF + 1); st_rel(&g_flagsB[c], baseB + 1); }

    const unsigned long long* w0pF = (const unsigned long long*)&Wsh[(0 * 8 + gate * 2 + 0) * 256];
    const unsigned long long* w1pF = (const unsigned long long*)&Wsh[(0 * 8 + gate * 2 + 1) * 256];
    const unsigned long long* w0pB = (const unsigned long long*)&Wsh[(1 * 8 + gate * 2 + 0) * 256];
    const unsigned long long* w1pB = (const unsigned long long*)&Wsh[(1 * 8 + gate * 2 + 1) * 256];
    const unsigned long long* hsp  = (const unsigned long long*)hs;   // [k2*64 + b]
    float4* hs4 = (float4*)hs;

    for (int s = 0; s < T_; s++) {
        const int p  = s & 1;
        const int tf = s;
        const int tb = T_ - 1 - s;

        // ================= phase F =================
        const float* gxF = g_Gx + (((long)0 * T_ + tf) * 4 + gate) * (256 * 64) + (2 * c) * 64 + b;
        float gaF0 = __ldg(gxF);
        float gaF1 = __ldg(gxF + 64);
        float mtF  = __ldg(mask + tf * B_ + b);

        if (tid < 128) {
            const unsigned* f = &g_flagsF[tid];
            while ((int)(ld_acq(f) - baseF) < (int)(s + 1)) { }
        }
        __syncthreads();

        {
            const float4* hin = (const float4*)(hbufF + p * 8192);
#pragma unroll
            for (int i = 0; i < 16; i++) hs4[tid + i * 256] = __ldcg(hin + tid + i * 256);
        }
        __syncthreads();

        unsigned long long a0 = 0ull, a1 = 0ull;
#pragma unroll 8
        for (int kk = 0; kk < 64; kk++) {
            unsigned long long hv0 = hsp[(2 * kk) * 64 + b];
            unsigned long long hv1 = hsp[(2 * kk + 1) * 64 + b];
            ulonglong2 w0 = ((const ulonglong2*)w0pF)[kk];
            ulonglong2 w1 = ((const ulonglong2*)w1pF)[kk];
            ffma2(a0, hv0, w0.x); ffma2(a0, hv1, w0.y);
            ffma2(a1, hv0, w1.x); ffma2(a1, hv1, w1.y);
        }
        {
            float2 q0 = upk(a0), q1 = upk(a1);
            ex[gate * 128 + 0 * 64 + b] = gaF0 + q0.x + q0.y;
            ex[gate * 128 + 1 * 64 + b] = gaF1 + q1.x + q1.y;
        }
        __syncthreads();

        if (tid < 128) {
            float ai = ex[0 * 128 + u * 64 + b];
            float af = ex[1 * 128 + u * 64 + b];
            float ag = ex[2 * 128 + u * 64 + b];
            float ao = ex[3 * 128 + u * 64 + b];
            float si = 1.f / (1.f + expf(-ai));
            float sf = 1.f / (1.f + expf(-af));
            float tg = tanhf(ag);
            float so = 1.f / (1.f + expf(-ao));
            float cn = sf * cF + si * tg;
            float hn = so * tanhf(cn);
            hF = mtF * hn + (1.f - mtF) * hF;
            cF = mtF * cn + (1.f - mtF) * cF;
            shp[u * 64 + b] = hF;
        }
        __syncthreads();
        if (tid < 64)
            __stcg(&hbufF[(1 - p) * 8192 + c * 64 + tid], make_float2(shp[tid], shp[64 + tid]));
        __syncthreads();
        if (tid == 0) st_rel(&g_flagsF[c], baseF + s + 2);
        if (tid < 128)
            g_Hout[(((long)0 * T_ + tf) * 256 + 2 * c + u) * 64 + b] = hF;

        // ================= phase B =================
        const float* gxB = g_Gx + (((long)1 * T_ + tb) * 4 + gate) * (256 * 64) + (2 * c) * 64 + b;
        float gaB0 = __ldg(gxB);
        float gaB1 = __ldg(gxB + 64);
        float mtB  = __ldg(mask + tb * B_ + b);

        if (tid < 128) {
            const unsigned* f = &g_flagsB[tid];
            while ((int)(ld_acq(f) - baseB) < (int)(s + 1)) { }
        }
        __syncthreads();

        {
            const float4* hin = (const float4*)(hbufB + p * 8192);
#pragma unroll
            for (int i = 0; i < 16; i++) hs4[tid + i * 256] = __ldcg(hin + tid + i * 256);
        }
        __syncthreads();

        unsigned long long b0 = 0ull, b1 = 0ull;
#pragma unroll 8
        for (int kk = 0; kk < 64; kk++) {
            unsigned long long hv0 = hsp[(2 * kk) * 64 + b];
            unsigned long long hv1 = hsp[(2 * kk + 1) * 64 + b];
            ulonglong2 w0 = ((const ulonglong2*)w0pB)[kk];
            ulonglong2 w1 = ((const ulonglong2*)w1pB)[kk];
            ffma2(b0, hv0, w0.x); ffma2(b0, hv1, w0.y);
            ffma2(b1, hv0, w1.x); ffma2(b1, hv1, w1.y);
        }
        {
            float2 q0 = upk(b0), q1 = upk(b1);
            ex[gate * 128 + 0 * 64 + b] = gaB0 + q0.x + q0.y;
            ex[gate * 128 + 1 * 64 + b] = gaB1 + q1.x + q1.y;
        }
        __syncthreads();

        if (tid < 128) {
            float ai = ex[0 * 128 + u * 64 + b];
            float af = ex[1 * 128 + u * 64 + b];
            float ag = ex[2 * 128 + u * 64 + b];
            float ao = ex[3 * 128 + u * 64 + b];
            float si = 1.f / (1.f + expf(-ai));
            float sf = 1.f / (1.f + expf(-af));
            float tg = tanhf(ag);
            float so = 1.f / (1.f + expf(-ao));
            float cn = sf * cB + si * tg;
            float hn = so * tanhf(cn);
            hB = mtB * hn + (1.f - mtB) * hB;
            cB = mtB * cn + (1.f - mtB) * cB;
            shp[u * 64 + b] = hB;
        }
        __syncthreads();
        if (tid < 64)
            __stcg(&hbufB[(1 - p) * 8192 + c * 64 + tid], make_float2(shp[tid], shp[64 + tid]));
        __syncthreads();
        if (tid == 0) st_rel(&g_flagsB[c], baseB + s + 2);
        if (tid < 128)
            g_Hout[(((long)1 * T_ + tb) * 256 + 2 * c + u) * 64 + b] = hB;
    }
}

// =====================================================================
// K3: feats[t][b][j] = (sum_k (h[k]*m) * Wtag[j][k] + btag[j]) * m
// =====================================================================
__global__ void feats_kernel(const float* __restrict__ Wtag,
                             const float* __restrict__ btag,
                             const float* __restrict__ mask)
{
    __shared__ float Ws[TAGS_ * 512];
    __shared__ float bts[TAGS_];
    const int t   = blockIdx.x;
    const int tid = threadIdx.x;
    for (int i = tid; i < TAGS_ * 512; i += 256) Ws[i] = Wtag[i];
    if (tid < TAGS_) bts[tid] = btag[tid];
    __syncthreads();

    const int w    = tid >> 5;
    const int lane = tid & 31;
    const float* Hf = g_Hout + ((long)t * 256) * 64;
    const float* Hb = g_Hout + ((long)T_ * 256 + (long)t * 256) * 64;
    for (int b = w; b < B_; b += 8) {
        float mt = mask[t * B_ + b];
        float acc[TAGS_];
#pragma unroll
        for (int j = 0; j < TAGS_; j++) acc[j] = 0.f;
        for (int k = lane; k < HD_; k += 32) {
            float hv  = Hf[k * 64 + b] * mt;
            float hv2 = Hb[k * 64 + b] * mt;
#pragma unroll
            for (int j = 0; j < TAGS_; j++) {
                acc[j] = fmaf(hv,  Ws[j * 512 + k],       acc[j]);
                acc[j] = fmaf(hv2, Ws[j * 512 + HD_ + k], acc[j]);
            }
        }
#pragma unroll
        for (int j = 0; j < TAGS_; j++)
#pragma unroll
            for (int off = 16; off > 0; off >>= 1)
                acc[j] += __shfl_xor_sync(0xffffffffu, acc[j], off);
        if (lane < TAGS_)
            g_feats[(t * B_ + b) * TAGS_ + lane] = (acc[lane] + bts[lane]) * mt;
    }
}

// =====================================================================
// K4: Viterbi. 1 CTA per batch element; feats + mask + ptrs in smem.
// =====================================================================
__global__ void viterbi_kernel(const float* __restrict__ trans,
                               const float* __restrict__ mask,
                               float* __restrict__ out, int out_size)
{
    __shared__ float fsh[T_ * TAGS_];
    __shared__ float msh[T_];
    __shared__ unsigned char ptrs[T_ * TAGS_];
    __shared__ float trs[TAGS_ * TAGS_];
    const int b   = blockIdx.x;
    const int tid = threadIdx.x;   // 128

    for (int i = tid; i < T_ * TAGS_; i += 128) {
        int t = i / TAGS_, j = i % TAGS_;
        fsh[i] = g_feats[(t * B_ + b) * TAGS_ + j];
    }
    for (int i = tid; i < T_; i += 128) msh[i] = mask[i * B_ + b];
    for (int i = tid; i < TAGS_ * TAGS_; i += 128) trs[i] = trans[i];
    __syncthreads();
    if (tid >= 32) return;

    const int j  = tid;
    const int jc = (j < TAGS_) ? j : 0;
    float score = (j == 9) ? 0.f : NEGV;   // START=9
    float trow[TAGS_];
#pragma unroll
    for (int q = 0; q < TAGS_; q++) trow[q] = trs[jc * TAGS_ + q];

    for (int t = 0; t < T_; t++) {
        float best = -1e30f;
        int arg = 0;
#pragma unroll
        for (int q = 0; q < TAGS_; q++) {
            float sq = __shfl_sync(0xffffffffu, score, q);
            float v = sq + trow[q];
            if (v > best) { best = v; arg = q; }
        }
        float mt = msh[t];
        float ns = best + fsh[t * TAGS_ + jc];
        if (j < TAGS_) {
            ptrs[t * TAGS_ + j] = (unsigned char)arg;
            if (mt > 0.f) score = ns;
        }
    }

    float fin = score + trs[10 * TAGS_ + jc];   // STOP=10
    float bs = -1e30f;
    int bt = 0;
#pragma unroll
    for (int q = 0; q < TAGS_; q++) {
        float v = __shfl_sync(0xffffffffu, fin, q);
        if (v > bs) { bs = v; bt = q; }
    }

    if (tid == 0) {
        if (out_size >= B_ * T_ + B_) out[B_ * T_ + b] = bs;
        int cur = bt;
        for (int t = T_ - 1; t >= 0; t--) {
            if (b * T_ + t < out_size) out[b * T_ + t] = (float)cur;
            cur = ptrs[t * TAGS_ + cur];
        }
    }
}

// =====================================================================
extern "C" void kernel_launch(void* const* d_in, const int* in_sizes, int n_in,
                              void* d_out, int out_size)
{
    const int*   sent  = (const int*)d_in[0];
    const float* mask  = (const float*)d_in[1];
    const float* embed = (const float*)d_in[2];
    const float* Wih_f = (const float*)d_in[3];
    const float* Whh_f = (const float*)d_in[4];
    const float* b_f   = (const float*)d_in[5];
    const float* Wih_b = (const float*)d_in[6];
    const float* Whh_b = (const float*)d_in[7];
    const float* b_b   = (const float*)d_in[8];
    const float* h0f   = (const float*)d_in[9];
    const float* c0f   = (const float*)d_in[10];
    const float* h0b   = (const float*)d_in[11];
    const float* c0b   = (const float*)d_in[12];
    const float* Wtag  = (const float*)d_in[13];
    const float* btag  = (const float*)d_in[14];
    const float* trans = (const float*)d_in[15];

    gx_kernel<<<dim3(T_, 16), 256>>>(sent, embed, Wih_f, b_f, Wih_b, b_b);

    cudaFuncSetAttribute(lstm_kernel, cudaFuncAttributeMaxDynamicSharedMemorySize, LSTM_SMEM);
    lstm_kernel<<<LSTM_NB, 256, LSTM_SMEM>>>(Whh_f, Whh_b, h0f, c0f, h0b, c0b, mask);

    feats_kernel<<<T_, 256>>>(Wtag, btag, mask);

    viterbi_kernel<<<B_, 128>>>(trans, mask, (float*)d_out, out_size);
}

// round 9
// speedup vs baseline: 1.2139x; 1.2139x over previous
#include <cuda_runtime.h>
#include <math.h>

#define B_    64
#define T_    512
#define EMB_  256
#define HD_   256
#define G4_   1024
#define TAGS_ 11
#define NEGV  (-10000.0f)
#define GSTRIDE (256 * 64)   // gate stride in g_Gx elements

// ---------------- scratch (static device globals; no allocs) ----------------
__device__ __align__(16) float g_Gx[(long)2 * T_ * B_ * G4_];   // [dir][t][gate][unit][b]
__device__ __align__(16) float g_Hout[(long)2 * T_ * B_ * HD_]; // [dir][t][unit][b]
__device__ __align__(16) float g_hbuf[2 * 2 * B_ * HD_];        // [dir][buf][unitq][b] float4
__device__ __align__(16) float g_feats[T_ * B_ * TAGS_];
#define LSTM_NB 128
__device__ unsigned g_flags[LSTM_NB];   // monotonic epochs across graph replays

// ---------------- packed f32x2 helpers ----------------
__device__ __forceinline__ void ffma2(unsigned long long& d,
                                      unsigned long long a,
                                      unsigned long long b) {
    asm("fma.rn.f32x2 %0, %1, %2, %0;" : "+l"(d) : "l"(a), "l"(b));
}
__device__ __forceinline__ float2 upk(unsigned long long v) {
    float2 f; asm("mov.b64 {%0, %1}, %2;" : "=f"(f.x), "=f"(f.y) : "l"(v)); return f;
}

// ---------------- fast activations (MUFU-based, ~1e-6 rel err) ----------------
__device__ __forceinline__ float sigf(float x) {
    return __fdividef(1.f, 1.f + __expf(-x));
}
__device__ __forceinline__ float tanhfast(float x) {
    return fmaf(2.f, __fdividef(1.f, 1.f + __expf(-2.f * x)), -1.f);
}

// ---------------- release/acquire flag ops ----------------
__device__ __forceinline__ unsigned ld_acq(const unsigned* p) {
    unsigned v;
    asm volatile("ld.global.acquire.gpu.u32 %0, [%1];" : "=r"(v) : "l"(p));
    return v;
}
__device__ __forceinline__ void st_rel(unsigned* p, unsigned v) {
    asm volatile("st.global.release.gpu.u32 [%0], %1;" :: "l"(p), "r"(v) : "memory");
}

// =====================================================================
// K1: Gx = embed[sent] @ Wih.T + b, written as [dir][t][gate][unit][b].
// Epilogue staged through smem tile [128 cols][64 b] (stride 68, 16B-aligned),
// then fully-coalesced float4 stores of ALL 128 columns.
// =====================================================================
#define GX_STAGE_FLOATS (128 * 68)   // 8704 floats >= As|Bs (6912)

__global__ void gx_kernel(const int* __restrict__ sent,
                          const float* __restrict__ embed,
                          const float* __restrict__ Wf, const float* __restrict__ bf,
                          const float* __restrict__ Wb, const float* __restrict__ bb)
{
    __shared__ __align__(16) float Sm[GX_STAGE_FLOATS];  // As | Bs, reused as stage
    float* As = Sm;                // [row][k] stride 36 (64*36 = 2304)
    float* Bs = Sm + 64 * 36;      // [col][k] stride 36 (128*36 = 4608, ends 6912)
    __shared__ int toks[64];

    const int t     = blockIdx.x;
    const int dir   = blockIdx.y >> 3;
    const int gcol0 = (blockIdx.y & 7) * 128;
    const float* __restrict__ W    = dir ? Wb : Wf;
    const float* __restrict__ bias = dir ? bb : bf;

    const int tid = threadIdx.x;
    if (tid < 64) toks[tid] = sent[tid * T_ + t];
    __syncthreads();

    const int rowg = tid & 7;
    const int colg = tid >> 3;

    unsigned long long acc[8][4];
#pragma unroll
    for (int i = 0; i < 8; i++)
#pragma unroll
        for (int j = 0; j < 4; j++) acc[i][j] = 0ull;

    for (int k0 = 0; k0 < EMB_; k0 += 32) {
#pragma unroll
        for (int i = 0; i < 2; i++) {
            int e = tid + i * 256, r = e >> 3, seg = e & 7;
            float4 va = *(const float4*)(embed + (long)toks[r] * EMB_ + k0 + seg * 4);
            *(float4*)&As[r * 36 + seg * 4] = va;
        }
#pragma unroll
        for (int i = 0; i < 4; i++) {
            int e = tid + i * 256, r = e >> 3, seg = e & 7;
            float4 vb = *(const float4*)(W + (long)(gcol0 + r) * EMB_ + k0 + seg * 4);
            *(float4*)&Bs[r * 36 + seg * 4] = vb;
        }
        __syncthreads();
#pragma unroll
        for (int k4 = 0; k4 < 8; k4++) {
            ulonglong2 bv[4];
#pragma unroll
            for (int j = 0; j < 4; j++)
                bv[j] = *(const ulonglong2*)&Bs[(colg * 4 + j) * 36 + k4 * 4];
#pragma unroll
            for (int i = 0; i < 8; i++) {
                ulonglong2 av = *(const ulonglong2*)&As[(rowg + 8 * i) * 36 + k4 * 4];
#pragma unroll
                for (int j = 0; j < 4; j++) {
                    ffma2(acc[i][j], av.x, bv[j].x);
                    ffma2(acc[i][j], av.y, bv[j].y);
                }
            }
        }
        __syncthreads();
    }
    __syncthreads();   // all reads of As/Bs done before reusing as stage

    // stage tile as [colLocal 0..127][b 0..63], stride 68 (272B, 16B multiple)
    float* stage = Sm;
#pragma unroll
    for (int j = 0; j < 4; j++) {
        int colL = colg * 4 + j;           // 0..127
        float bsv = bias[gcol0 + colL];
#pragma unroll
        for (int i = 0; i < 8; i++) {
            float2 p = upk(acc[i][j]);
            stage[colL * 68 + rowg + 8 * i] = p.x + p.y + bsv;
        }
    }
    __syncthreads();

    const long tb = (long)dir * T_ + t;
#pragma unroll
    for (int i = 0; i < 8; i++) {
        int id   = tid + i * 256;          // 0..2047 float4 units (128 cols x 16)
        int colL = id >> 4;                // 0..127
        int b4   = id & 15;
        int gcol = gcol0 + colL;
        long obase = ((tb * 4 + (gcol >> 8)) * 256 + (gcol & 255)) * 64;
        float4 v = *(float4*)&stage[colL * 68 + b4 * 4];
        *(float4*)(g_Gx + obase + b4 * 4) = v;
    }
}

// =====================================================================
// K2: persistent bidirectional LSTM, 128 CTAs x 256 threads (R3 structure).
// CTA = (dir, kq 4-unit group); thread b=tid&63, u=tid>>6.
// Half-split barrier: wait/stage/compute producers 0-31, then 32-63.
// Fast MUFU activations. Hout off critical path.
// =====================================================================
#define WSTRIDE   260
#define SM_WSH    0
#define SM_HS4    (16 * WSTRIDE)
#define SM_SHH    (SM_HS4 + 64 * 64 * 4)
#define LSTM_SMEM ((SM_SHH + 256) * 4)

__global__ void __launch_bounds__(256, 1)
lstm_kernel(const float* __restrict__ Whh_f, const float* __restrict__ Whh_b,
            const float* __restrict__ h0f, const float* __restrict__ c0f,
            const float* __restrict__ h0b, const float* __restrict__ c0b,
            const float* __restrict__ mask)
{
    extern __shared__ __align__(16) float sm[];
    float*  Wsh  = sm + SM_WSH;
    float4* hs4  = (float4*)(sm + SM_HS4);
    float*  sh_h = sm + SM_SHH;

    const int cta = blockIdx.x;
    const int dir = cta >> 6;
    const int kq  = cta & 63;
    const int u0  = kq * 4;
    const int tid = threadIdx.x;
    const int b    = tid & 63;
    const int u    = tid >> 6;
    const int unit = u0 + u;

    const float* __restrict__ Whh = dir ? Whh_b : Whh_f;
    const float* __restrict__ h0  = dir ? h0b : h0f;
    const float* __restrict__ c0  = dir ? c0b : c0f;

    float4* hbuf0 = ((float4*)g_hbuf) + (dir * 2 + 0) * (64 * 64);
    float4* hbuf1 = ((float4*)g_hbuf) + (dir * 2 + 1) * (64 * 64);
    float4* HoutD = ((float4*)g_Hout) + (long)dir * T_ * 64 * 64;
    unsigned* myflag = &g_flags[cta];
    const unsigned* dflags = &g_flags[dir * 64];

    __shared__ unsigned sbase;
    if (tid == 0) sbase = ld_acq(myflag);
    __syncthreads();
    const unsigned base = sbase;

    // preload weight slice: Wsh[g*4+uu][k] = Whh[g*256 + u0+uu][k]
#pragma unroll
    for (int i = 0; i < 4; i++) {
        int f  = tid + i * 256;
        int r  = f >> 6;
        int k4 = f & 63;
        int grow = (r >> 2) * HD_ + u0 + (r & 3);
        float4 w = *(const float4*)(Whh + (long)grow * HD_ + k4 * 4);
        *(float4*)&Wsh[r * WSTRIDE + k4 * 4] = w;
    }

    float c = c0[b * HD_ + unit];
    float h = h0[b * HD_ + unit];

    sh_h[u * 64 + b] = h;
    __syncthreads();
    if (tid < 64) {
        float4 v = make_float4(sh_h[tid], sh_h[64 + tid], sh_h[128 + tid], sh_h[192 + tid]);
        __stcg(&hbuf0[kq * 64 + tid], v);
    }
    __syncthreads();
    if (tid == 0) st_rel(myflag, base + 1);

    const float* w0p = &Wsh[(0 + u) * WSTRIDE];
    const float* w1p = &Wsh[(4 + u) * WSTRIDE];
    const float* w2p = &Wsh[(8 + u) * WSTRIDE];
    const float* w3p = &Wsh[(12 + u) * WSTRIDE];
    const unsigned long long* hsp = (const unsigned long long*)hs4;

    for (int s = 0; s < T_; s++) {
        const int t = dir ? (T_ - 1 - s) : s;
        const int p = s & 1;

        // prefetch gate pre-activations + mask (independent of barrier)
        const float* gx = g_Gx + (((long)dir * T_ + t) * 4 * 256 + unit) * 64 + b;
        float ga0 = __ldg(gx);
        float ga1 = __ldg(gx + GSTRIDE);
        float ga2 = __ldg(gx + 2 * GSTRIDE);
        float ga3 = __ldg(gx + 3 * GSTRIDE);
        float mt  = __ldg(mask + t * B_ + b);

        const float4* hin = p ? hbuf1 : hbuf0;
        unsigned long long a0p = 0ull, a1p = 0ull, a2p = 0ull, a3p = 0ull;

        // ---- first half: producers 0..31 (covers kq 0..31 => e < 2048) ----
        if (tid < 32) {
            const unsigned* f = dflags + tid;
            while ((int)(ld_acq(f) - base) < (int)(s + 1)) { }
        }
        __syncthreads();
#pragma unroll
        for (int i = 0; i < 8; i++) {
            int e = tid + i * 256;
            hs4[e] = __ldcg(hin + e);
        }
        __syncthreads();
#pragma unroll 8
        for (int kk = 0; kk < 32; kk++) {
            unsigned long long hv0 = hsp[(2 * kk) * 64 + b];
            unsigned long long hv1 = hsp[(2 * kk + 1) * 64 + b];
            ulonglong2 w0 = *(const ulonglong2*)&w0p[kk * 4];
            ulonglong2 w1 = *(const ulonglong2*)&w1p[kk * 4];
            ulonglong2 w2 = *(const ulonglong2*)&w2p[kk * 4];
            ulonglong2 w3 = *(const ulonglong2*)&w3p[kk * 4];
            ffma2(a0p, hv0, w0.x); ffma2(a0p, hv1, w0.y);
            ffma2(a1p, hv0, w1.x); ffma2(a1p, hv1, w1.y);
            ffma2(a2p, hv0, w2.x); ffma2(a2p, hv1, w2.y);
            ffma2(a3p, hv0, w3.x); ffma2(a3p, hv1, w3.y);
        }

        // ---- second half: producers 32..63 ----
        if (tid >= 32 && tid < 64) {
            const unsigned* f = dflags + tid;
            while ((int)(ld_acq(f) - base) < (int)(s + 1)) { }
        }
        __syncthreads();
#pragma unroll
        for (int i = 8; i < 16; i++) {
            int e = tid + i * 256;
            hs4[e] = __ldcg(hin + e);
        }
        __syncthreads();
#pragma unroll 8
        for (int kk = 32; kk < 64; kk++) {
            unsigned long long hv0 = hsp[(2 * kk) * 64 + b];
            unsigned long long hv1 = hsp[(2 * kk + 1) * 64 + b];
            ulonglong2 w0 = *(const ulonglong2*)&w0p[kk * 4];
            ulonglong2 w1 = *(const ulonglong2*)&w1p[kk * 4];
            ulonglong2 w2 = *(const ulonglong2*)&w2p[kk * 4];
            ulonglong2 w3 = *(const ulonglong2*)&w3p[kk * 4];
            ffma2(a0p, hv0, w0.x); ffma2(a0p, hv1, w0.y);
            ffma2(a1p, hv0, w1.x); ffma2(a1p, hv1, w1.y);
            ffma2(a2p, hv0, w2.x); ffma2(a2p, hv1, w2.y);
            ffma2(a3p, hv0, w3.x); ffma2(a3p, hv1, w3.y);
        }

        float2 q0 = upk(a0p), q1 = upk(a1p), q2 = upk(a2p), q3 = upk(a3p);
        float a0 = ga0 + q0.x + q0.y;
        float a1 = ga1 + q1.x + q1.y;
        float a2 = ga2 + q2.x + q2.y;
        float a3 = ga3 + q3.x + q3.y;

        float si = sigf(a0);
        float sf = sigf(a1);
        float tg = tanhfast(a2);
        float so = sigf(a3);
        float cn = sf * c + si * tg;
        float hn = so * tanhfast(cn);
        h = mt * hn + (1.f - mt) * h;
        c = mt * cn + (1.f - mt) * c;

        sh_h[u * 64 + b] = h;
        __syncthreads();
        float4 v;
        if (tid < 64) {
            v = make_float4(sh_h[tid], sh_h[64 + tid], sh_h[128 + tid], sh_h[192 + tid]);
            __stcg(&((p ? hbuf0 : hbuf1)[kq * 64 + tid]), v);
        }
        __syncthreads();
        if (tid == 0) st_rel(myflag, base + s + 2);

        if (tid < 64)
            HoutD[((long)t * 64 + kq) * 64 + tid] = v;
    }
}

// =====================================================================
// K3: feats[t][b][j] = (sum_k (h[k]*m) * Wtag[j][k] + btag[j]) * m
// =====================================================================
__global__ void feats_kernel(const float* __restrict__ Wtag,
                             const float* __restrict__ btag,
                             const float* __restrict__ mask)
{
    __shared__ float Ws[TAGS_ * 512];
    __shared__ float bts[TAGS_];
    const int t   = blockIdx.x;
    const int tid = threadIdx.x;
    for (int i = tid; i < TAGS_ * 512; i += 256) Ws[i] = Wtag[i];
    if (tid < TAGS_) bts[tid] = btag[tid];
    __syncthreads();

    const int w    = tid >> 5;
    const int lane = tid & 31;
    const float* Hf = g_Hout + ((long)t * 256) * 64;
    const float* Hb = g_Hout + ((long)T_ * 256 + (long)t * 256) * 64;
    for (int b = w; b < B_; b += 8) {
        float mt = mask[t * B_ + b];
        float acc[TAGS_];
#pragma unroll
        for (int j = 0; j < TAGS_; j++) acc[j] = 0.f;
        for (int k = lane; k < HD_; k += 32) {
            float hv  = Hf[k * 64 + b] * mt;
            float hv2 = Hb[k * 64 + b] * mt;
#pragma unroll
            for (int j = 0; j < TAGS_; j++) {
                acc[j] = fmaf(hv,  Ws[j * 512 + k],       acc[j]);
                acc[j] = fmaf(hv2, Ws[j * 512 + HD_ + k], acc[j]);
            }
        }
#pragma unroll
        for (int j = 0; j < TAGS_; j++)
#pragma unroll
            for (int off = 16; off > 0; off >>= 1)
                acc[j] += __shfl_xor_sync(0xffffffffu, acc[j], off);
        if (lane < TAGS_)
            g_feats[(t * B_ + b) * TAGS_ + lane] = (acc[lane] + bts[lane]) * mt;
    }
}

// =====================================================================
// K4: Viterbi. 1 CTA/batch. Full score vector replicated per lane;
// tournament-tree argmax in registers; independent broadcast shfls.
// =====================================================================
__global__ void viterbi_kernel(const float* __restrict__ trans,
                               const float* __restrict__ mask,
                               float* __restrict__ out, int out_size)
{
    __shared__ float fsh[T_ * TAGS_];
    __shared__ float msh[T_];
    __shared__ unsigned char ptrs[T_ * TAGS_];
    __shared__ float trs[TAGS_ * TAGS_];
    const int bb  = blockIdx.x;
    const int tid = threadIdx.x;   // 128

    for (int i = tid; i < T_ * TAGS_; i += 128) {
        int t = i / TAGS_, j = i % TAGS_;
        fsh[i] = g_feats[(t * B_ + bb) * TAGS_ + j];
    }
    for (int i = tid; i < T_; i += 128) msh[i] = mask[i * B_ + bb];
    for (int i = tid; i < TAGS_ * TAGS_; i += 128) trs[i] = trans[i];
    __syncthreads();
    if (tid >= 32) return;

    const int j  = tid;
    const int jc = (j < TAGS_) ? j : 0;
    float trow[TAGS_];
#pragma unroll
    for (int q = 0; q < TAGS_; q++) trow[q] = trs[jc * TAGS_ + q];

    float s[TAGS_];
#pragma unroll
    for (int q = 0; q < TAGS_; q++) s[q] = (q == 9) ? 0.f : NEGV;   // START=9

    for (int t = 0; t < T_; t++) {
        float v[16]; int ix[16];
#pragma unroll
        for (int q = 0; q < TAGS_; q++) { v[q] = s[q] + trow[q]; ix[q] = q; }
#pragma unroll
        for (int q = TAGS_; q < 16; q++) { v[q] = -1e30f; ix[q] = q; }
#pragma unroll
        for (int st = 1; st < 16; st <<= 1)
#pragma unroll
            for (int q = 0; q < 16; q += 2 * st) {
                bool rt = v[q + st] > v[q];
                v[q]  = rt ? v[q + st] : v[q];
                ix[q] = rt ? ix[q + st] : ix[q];
            }
        float ns = v[0] + fsh[t * TAGS_ + jc];
        if (j < TAGS_) ptrs[t * TAGS_ + j] = (unsigned char)ix[0];
        float mt = msh[t];
        float sn = (mt > 0.f) ? ns : s[jc];
#pragma unroll
        for (int q = 0; q < TAGS_; q++)
            s[q] = __shfl_sync(0xffffffffu, sn, q);
    }

    float fv[16]; int fix[16];
#pragma unroll
    for (int q = 0; q < TAGS_; q++) { fv[q] = s[q] + trs[10 * TAGS_ + q]; fix[q] = q; }
#pragma unroll
    for (int q = TAGS_; q < 16; q++) { fv[q] = -1e30f; fix[q] = q; }
#pragma unroll
    for (int st = 1; st < 16; st <<= 1)
#pragma unroll
        for (int q = 0; q < 16; q += 2 * st) {
            bool rt = fv[q + st] > fv[q];
            fv[q]  = rt ? fv[q + st] : fv[q];
            fix[q] = rt ? fix[q + st] : fix[q];
        }

    if (tid == 0) {
        if (out_size >= B_ * T_ + B_) out[B_ * T_ + bb] = fv[0];
        int cur = fix[0];
        for (int t = T_ - 1; t >= 0; t--) {
            if (bb * T_ + t < out_size) out[bb * T_ + t] = (float)cur;
            cur = ptrs[t * TAGS_ + cur];
        }
    }
}

// =====================================================================
extern "C" void kernel_launch(void* const* d_in, const int* in_sizes, int n_in,
                              void* d_out, int out_size)
{
    const int*   sent  = (const int*)d_in[0];
    const float* mask  = (const float*)d_in[1];
    const float* embed = (const float*)d_in[2];
    const float* Wih_f = (const float*)d_in[3];
    const float* Whh_f = (const float*)d_in[4];
    const float* b_f   = (const float*)d_in[5];
    const float* Wih_b = (const float*)d_in[6];
    const float* Whh_b = (const float*)d_in[7];
    const float* b_b   = (const float*)d_in[8];
    const float* h0f   = (const float*)d_in[9];
    const float* c0f   = (const float*)d_in[10];
    const float* h0b   = (const float*)d_in[11];
    const float* c0b   = (const float*)d_in[12];
    const float* Wtag  = (const float*)d_in[13];
    const float* btag  = (const float*)d_in[14];
    const float* trans = (const float*)d_in[15];

    gx_kernel<<<dim3(T_, 16), 256>>>(sent, embed, Wih_f, b_f, Wih_b, b_b);

    cudaFuncSetAttribute(lstm_kernel, cudaFuncAttributeMaxDynamicSharedMemorySize, LSTM_SMEM);
    lstm_kernel<<<LSTM_NB, 256, LSTM_SMEM>>>(Whh_f, Whh_b, h0f, c0f, h0b, c0b, mask);

    feats_kernel<<<T_, 256>>>(Wtag, btag, mask);

    viterbi_kernel<<<B_, 128>>>(trans, mask, (float*)d_out, out_size);
}